// round 1
// baseline (speedup 1.0000x reference)
#include <cuda_runtime.h>

#define BATCH 16
#define TLEN  512
#define DIMSZ 384
#define DMAX  4096
#define MAIN  (BATCH * DIMSZ * DMAX)   // 25,165,824 floats

// Scratch: per-(batch, frame) source timestep index, -1 = pad.
__device__ int g_idx[BATCH * DMAX];

// ---------------------------------------------------------------------------
// Kernel 1: block per batch. Inclusive scan of durations, scatter timestep
// index into frame ranges, write mel_len into d_out tail.
// ---------------------------------------------------------------------------
__global__ void __launch_bounds__(TLEN) build_idx_kernel(
    const int* __restrict__ dur, float* __restrict__ out, int out_size)
{
    const int b = blockIdx.x;
    const int t = threadIdx.x;          // 0..511
    int d = dur[b * TLEN + t];

    const int lane = t & 31;
    const int wid  = t >> 5;            // 0..15

    // warp inclusive scan
    int v = d;
    #pragma unroll
    for (int o = 1; o < 32; o <<= 1) {
        int n = __shfl_up_sync(0xffffffffu, v, o);
        if (lane >= o) v += n;
    }

    __shared__ int wsum[16], woff[16];
    if (lane == 31) wsum[wid] = v;
    __syncthreads();

    if (t < 16) {
        int w = wsum[t];
        #pragma unroll
        for (int o = 1; o < 16; o <<= 1) {
            int n = __shfl_up_sync(0x0000ffffu, w, o);
            if (t >= o) w += n;
        }
        woff[t] = w;
    }
    __syncthreads();

    const int total = woff[15];
    int cum, mel;
    if (total == 0) {                   // all-zero row: duration := 1 everywhere
        d   = 1;
        cum = t + 1;
        mel = TLEN;
    } else {
        cum = v + (wid ? woff[wid - 1] : 0);
        mel = total;
    }

    // init idx to -1 (pad sentinel)
    #pragma unroll
    for (int f = t; f < DMAX; f += TLEN) g_idx[b * DMAX + f] = -1;
    __syncthreads();

    // scatter: frames [cum-d, cum) come from timestep t (disjoint ranges,
    // zero-duration timesteps write nothing -> matches searchsorted 'right')
    const int start = cum - d;
    for (int k = 0; k < d; k++) g_idx[b * DMAX + start + k] = t;

    // mel_len (second tuple output) appended after the main tensor, as float
    if (t == 0 && out_size >= MAIN + BATCH) {
        out[MAIN + b] = (float)mel;
    }
    // zero any extra tail beyond the two outputs (d_out is poisoned 0xAA)
    if (b == 0) {
        for (int p = MAIN + BATCH + t; p < out_size; p += TLEN) out[p] = 0.0f;
    }
}

// ---------------------------------------------------------------------------
// Kernel 2: expansion. grid = (8 f-tiles of 512 frames, 4 d-chunks of 96 rows,
// 16 batches) = 512 blocks x 256 threads. Frame indices are staged in smem and
// hoisted out of the d-loop (invariant per thread). One float4 store / thread
// / row -> fully coalesced 100 MB write stream.
// ---------------------------------------------------------------------------
__global__ void __launch_bounds__(256) expand_kernel(
    const float* __restrict__ x, float* __restrict__ out)
{
    const int b      = blockIdx.z;
    const int ftile  = blockIdx.x;      // 0..7
    const int dchunk = blockIdx.y;      // 0..3
    const int tid    = threadIdx.x;

    __shared__ int s_idx[512];
    const int* gi = g_idx + b * DMAX + ftile * 512;
    s_idx[tid]       = gi[tid];
    s_idx[tid + 256] = gi[tid + 256];
    __syncthreads();

    const int fq   = tid & 127;         // float4 slot within 512-frame tile
    const int dsel = tid >> 7;          // 0 or 1: which of 2 rows per iter
    const int f    = fq * 4;

    const int i0 = s_idx[f];
    const int i1 = s_idx[f + 1];
    const int i2 = s_idx[f + 2];
    const int i3 = s_idx[f + 3];

    const float* xb = x   + (size_t)b * DIMSZ * TLEN;
    float*       ob = out + (size_t)b * DIMSZ * DMAX + ftile * 512;

    const int d0 = dchunk * 96 + dsel;
    #pragma unroll 4
    for (int dd = 0; dd < 96; dd += 2) {
        const int d = d0 + dd;
        const float* __restrict__ xr = xb + d * TLEN;
        float4 val;
        val.x = (i0 >= 0) ? __ldg(xr + i0) : 0.0f;
        val.y = (i1 >= 0) ? __ldg(xr + i1) : 0.0f;
        val.z = (i2 >= 0) ? __ldg(xr + i2) : 0.0f;
        val.w = (i3 >= 0) ? __ldg(xr + i3) : 0.0f;
        *reinterpret_cast<float4*>(ob + (size_t)d * DMAX + f) = val;
    }
}

extern "C" void kernel_launch(void* const* d_in, const int* in_sizes, int n_in,
                              void* d_out, int out_size)
{
    const float* x   = (const float*)d_in[0];   // (16, 384, 512) f32
    const int*   dur = (const int*)d_in[1];     // (16, 512) i32
    float*       out = (float*)d_out;

    build_idx_kernel<<<BATCH, TLEN>>>(dur, out, out_size);
    expand_kernel<<<dim3(8, 4, BATCH), 256>>>(x, out);
}

// round 2
// speedup vs baseline: 1.4717x; 1.4717x over previous
#include <cuda_runtime.h>

#define BATCH 16
#define TLEN  512
#define DIMSZ 384
#define DMAX  4096
#define MAIN  (BATCH * DIMSZ * DMAX)   // 25,165,824 floats

// Scratch: per-(batch, frame) source timestep index, -1 = pad.
__device__ int g_idx[BATCH * DMAX];

// ---------------------------------------------------------------------------
// Kernel 1: block per batch. Inclusive scan of durations, scatter timestep
// index into frame ranges, write mel_len into d_out tail.
// ---------------------------------------------------------------------------
__global__ void __launch_bounds__(TLEN) build_idx_kernel(
    const int* __restrict__ dur, float* __restrict__ out, int out_size)
{
    const int b = blockIdx.x;
    const int t = threadIdx.x;          // 0..511
    int d = dur[b * TLEN + t];

    const int lane = t & 31;
    const int wid  = t >> 5;            // 0..15

    // warp inclusive scan
    int v = d;
    #pragma unroll
    for (int o = 1; o < 32; o <<= 1) {
        int n = __shfl_up_sync(0xffffffffu, v, o);
        if (lane >= o) v += n;
    }

    __shared__ int wsum[16], woff[16];
    if (lane == 31) wsum[wid] = v;
    __syncthreads();

    if (t < 16) {
        int w = wsum[t];
        #pragma unroll
        for (int o = 1; o < 16; o <<= 1) {
            int n = __shfl_up_sync(0x0000ffffu, w, o);
            if (t >= o) w += n;
        }
        woff[t] = w;
    }
    __syncthreads();

    const int total = woff[15];
    int cum, mel;
    if (total == 0) {                   // all-zero row: duration := 1 everywhere
        d   = 1;
        cum = t + 1;
        mel = TLEN;
    } else {
        cum = v + (wid ? woff[wid - 1] : 0);
        mel = total;
    }

    // init idx to -1 (pad sentinel)
    #pragma unroll
    for (int f = t; f < DMAX; f += TLEN) g_idx[b * DMAX + f] = -1;
    __syncthreads();

    // scatter: frames [cum-d, cum) come from timestep t (disjoint ranges,
    // zero-duration timesteps write nothing -> matches searchsorted 'right')
    const int start = cum - d;
    for (int k = 0; k < d; k++) g_idx[b * DMAX + start + k] = t;

    // mel_len (second tuple output) appended after the main tensor, as float
    if (t == 0 && out_size >= MAIN + BATCH) {
        out[MAIN + b] = (float)mel;
    }
    // zero any extra tail beyond the two outputs (d_out is poisoned 0xAA)
    if (b == 0) {
        for (int p = MAIN + BATCH + t; p < out_size; p += TLEN) out[p] = 0.0f;
    }
}

// ---------------------------------------------------------------------------
// Kernel 2: expansion. grid = (8 f-tiles of 512 frames, 16 d-chunks of 24
// rows, 16 batches) = 2048 blocks x 256 threads (16384 warps -> 2 full
// waves). Frame indices hoisted out of the fully-unrolled d-loop; gathers
// batched for MLP; output written with streaming stores (write-once data,
// keep L2 for the x rows).
// ---------------------------------------------------------------------------
__global__ void __launch_bounds__(256) expand_kernel(
    const float* __restrict__ x, float* __restrict__ out)
{
    const int b      = blockIdx.z;
    const int ftile  = blockIdx.x;      // 0..7
    const int dchunk = blockIdx.y;      // 0..15 (24 rows each)
    const int tid    = threadIdx.x;

    __shared__ int s_idx[512];
    const int* gi = g_idx + b * DMAX + ftile * 512;
    s_idx[tid]       = gi[tid];
    s_idx[tid + 256] = gi[tid + 256];
    __syncthreads();

    const int fq   = tid & 127;         // float4 slot within 512-frame tile
    const int dsel = tid >> 7;          // 0 or 1: which of 2 rows per iter
    const int f    = fq * 4;

    const int i0 = s_idx[f];
    const int i1 = s_idx[f + 1];
    const int i2 = s_idx[f + 2];
    const int i3 = s_idx[f + 3];

    const float* xb = x   + (size_t)b * DIMSZ * TLEN;
    float*       ob = out + (size_t)b * DIMSZ * DMAX + ftile * 512;

    const int d0 = dchunk * 24 + dsel;
    #pragma unroll
    for (int dd = 0; dd < 24; dd += 2) {
        const int d = d0 + dd;
        const float* __restrict__ xr = xb + d * TLEN;
        float4 val;
        val.x = (i0 >= 0) ? __ldg(xr + i0) : 0.0f;
        val.y = (i1 >= 0) ? __ldg(xr + i1) : 0.0f;
        val.z = (i2 >= 0) ? __ldg(xr + i2) : 0.0f;
        val.w = (i3 >= 0) ? __ldg(xr + i3) : 0.0f;
        __stcs(reinterpret_cast<float4*>(ob + (size_t)d * DMAX + f), val);
    }
}

extern "C" void kernel_launch(void* const* d_in, const int* in_sizes, int n_in,
                              void* d_out, int out_size)
{
    const float* x   = (const float*)d_in[0];   // (16, 384, 512) f32
    const int*   dur = (const int*)d_in[1];     // (16, 512) i32
    float*       out = (float*)d_out;

    build_idx_kernel<<<BATCH, TLEN>>>(dur, out, out_size);
    expand_kernel<<<dim3(8, 16, BATCH), 256>>>(x, out);
}

// round 3
// speedup vs baseline: 1.4780x; 1.0043x over previous
#include <cuda_runtime.h>

#define BATCH 16
#define TLEN  512
#define DIMSZ 384
#define DMAX  4096
#define MAIN  (BATCH * DIMSZ * DMAX)   // 25,165,824 floats

// Scratch: per-(batch, frame) source timestep index, -1 = pad.
__device__ int g_idx[BATCH * DMAX];
__device__ int g_mel[BATCH];

// ---------------------------------------------------------------------------
// Kernel 1: block per batch. Inclusive scan of durations, scatter timestep
// index into frame ranges, write mel_len into d_out tail + g_mel.
// ---------------------------------------------------------------------------
__global__ void __launch_bounds__(TLEN) build_idx_kernel(
    const int* __restrict__ dur, float* __restrict__ out, int out_size)
{
    const int b = blockIdx.x;
    const int t = threadIdx.x;          // 0..511
    int d = dur[b * TLEN + t];

    const int lane = t & 31;
    const int wid  = t >> 5;            // 0..15

    // warp inclusive scan
    int v = d;
    #pragma unroll
    for (int o = 1; o < 32; o <<= 1) {
        int n = __shfl_up_sync(0xffffffffu, v, o);
        if (lane >= o) v += n;
    }

    __shared__ int wsum[16], woff[16];
    if (lane == 31) wsum[wid] = v;
    __syncthreads();

    if (t < 16) {
        int w = wsum[t];
        #pragma unroll
        for (int o = 1; o < 16; o <<= 1) {
            int n = __shfl_up_sync(0x0000ffffu, w, o);
            if (t >= o) w += n;
        }
        woff[t] = w;
    }
    __syncthreads();

    const int total = woff[15];
    int cum, mel;
    if (total == 0) {                   // all-zero row: duration := 1 everywhere
        d   = 1;
        cum = t + 1;
        mel = TLEN;
    } else {
        cum = v + (wid ? woff[wid - 1] : 0);
        mel = total;
    }

    // init idx to -1 (pad sentinel)
    #pragma unroll
    for (int f = t; f < DMAX; f += TLEN) g_idx[b * DMAX + f] = -1;
    __syncthreads();

    // scatter: frames [cum-d, cum) come from timestep t (disjoint ranges,
    // zero-duration timesteps write nothing -> matches searchsorted 'right')
    const int start = cum - d;
    for (int k = 0; k < d; k++) g_idx[b * DMAX + start + k] = t;

    if (t == 0) {
        g_mel[b] = mel;
        // mel_len (second tuple output) appended after main tensor, as float
        if (out_size >= MAIN + BATCH) out[MAIN + b] = (float)mel;
    }
    // zero any extra tail beyond the two outputs (d_out is poisoned 0xAA)
    if (b == 0) {
        for (int p = MAIN + BATCH + t; p < out_size; p += TLEN) out[p] = 0.0f;
    }
}

// ---------------------------------------------------------------------------
// Kernel 2: expansion. grid = (8 f-tiles of 512 frames, 16 d-chunks of 24
// rows, 16 batches) = 2048 blocks x 256 threads.
// Fast path: tiles entirely past mel_len are pure zero-store streams (no
// gathers, no smem, no scoreboard stalls) -- >half the output on average.
// Slow path: indices staged in smem, hoisted to registers, fully unrolled
// d-loop with <=64 regs so ptxas batches ~8 gathers in flight.
// ---------------------------------------------------------------------------
__global__ void __launch_bounds__(256, 4) expand_kernel(
    const float* __restrict__ x, float* __restrict__ out)
{
    const int b      = blockIdx.z;
    const int ftile  = blockIdx.x;      // 0..7
    const int dchunk = blockIdx.y;      // 0..15 (24 rows each)
    const int tid    = threadIdx.x;

    const int fq   = tid & 127;         // float4 slot within 512-frame tile
    const int dsel = tid >> 7;          // 0 or 1: which of 2 rows per iter
    const int f    = fq * 4;
    const int d0   = dchunk * 24 + dsel;

    float* ob = out + (size_t)b * DIMSZ * DMAX + ftile * 512;

    // ---- fast path: whole tile is padding -> zero stores only ----
    if (ftile * 512 >= g_mel[b]) {
        const float4 z = make_float4(0.f, 0.f, 0.f, 0.f);
        #pragma unroll
        for (int dd = 0; dd < 24; dd += 2) {
            __stcs(reinterpret_cast<float4*>(ob + (size_t)(d0 + dd) * DMAX + f), z);
        }
        return;
    }

    // ---- slow path: gather ----
    __shared__ int s_idx[512];
    const int* gi = g_idx + b * DMAX + ftile * 512;
    s_idx[tid]       = gi[tid];
    s_idx[tid + 256] = gi[tid + 256];
    __syncthreads();

    const int i0 = s_idx[f];
    const int i1 = s_idx[f + 1];
    const int i2 = s_idx[f + 2];
    const int i3 = s_idx[f + 3];

    const float* xb = x + (size_t)b * DIMSZ * TLEN;

    #pragma unroll
    for (int dd = 0; dd < 24; dd += 2) {
        const int d = d0 + dd;
        const float* __restrict__ xr = xb + d * TLEN;
        float4 val;
        val.x = (i0 >= 0) ? __ldg(xr + i0) : 0.0f;
        val.y = (i1 >= 0) ? __ldg(xr + i1) : 0.0f;
        val.z = (i2 >= 0) ? __ldg(xr + i2) : 0.0f;
        val.w = (i3 >= 0) ? __ldg(xr + i3) : 0.0f;
        __stcs(reinterpret_cast<float4*>(ob + (size_t)d * DMAX + f), val);
    }
}

extern "C" void kernel_launch(void* const* d_in, const int* in_sizes, int n_in,
                              void* d_out, int out_size)
{
    const float* x   = (const float*)d_in[0];   // (16, 384, 512) f32
    const int*   dur = (const int*)d_in[1];     // (16, 512) i32
    float*       out = (float*)d_out;

    build_idx_kernel<<<BATCH, TLEN>>>(dur, out, out_size);
    expand_kernel<<<dim3(8, 16, BATCH), 256>>>(x, out);
}